// round 14
// baseline (speedup 1.0000x reference)
#include <cuda_runtime.h>

#define BB 8
#define HH 128
#define WWD 128
#define DD4 128          // D / 4 (float4 lanes)

// Scratch (allocation-free rule: __device__ globals)
__device__ float4 g_partial[BB * HH * 5 * DD4];  // [b][h][k][d4], k=0..3 w-region sums, k=4 full row
__device__ float4 g_sums[BB * 17 * DD4];         // [b][r][d4], r=0..15 region sums, r=16 global

__device__ __forceinline__ float4 f4add(float4 a, float4 b) {
    return make_float4(a.x + b.x, a.y + b.y, a.z + b.z, a.w + b.w);
}
__device__ __forceinline__ float4 f4fma(float s, float4 a, float4 b) {
    return make_float4(fmaf(s, a.x, b.x), fmaf(s, a.y, b.y),
                       fmaf(s, a.z, b.z), fmaf(s, a.w, b.w));
}

// ---------------------------------------------------------------------------
// k1: per (b,h) row — per-w-region partial sums + full row sum.
// grid = B*H = 1024 blocks, 128 threads. Proven fastest form (~45us).
// ---------------------------------------------------------------------------
__global__ __launch_bounds__(128) void k1_rowsums(const float4* __restrict__ feat) {
    const int bh = blockIdx.x;                 // b*128 + h
    const int t  = threadIdx.x;                // d4 lane
    const float4* row = feat + (size_t)bh * WWD * DD4 + t;

    float4 a0 = make_float4(0.f, 0.f, 0.f, 0.f);
    float4 a1 = a0, a2 = a0, a3 = a0, af = a0;

    #pragma unroll 4
    for (int w = 0; w < WWD; ++w) {
        float4 v = __ldg(&row[(size_t)w * DD4]);
        af = f4add(af, v);
        // region j covers w in [24j, 24j+32)
        if (w < 32)             a0 = f4add(a0, v);
        if (w >= 24 && w < 56)  a1 = f4add(a1, v);
        if (w >= 48 && w < 80)  a2 = f4add(a2, v);
        if (w >= 72 && w < 104) a3 = f4add(a3, v);
    }

    float4* p = g_partial + (size_t)bh * 5 * DD4 + t;
    p[0 * DD4] = a0;
    p[1 * DD4] = a1;
    p[2 * DD4] = a2;
    p[3 * DD4] = a3;
    p[4 * DD4] = af;
}

// ---------------------------------------------------------------------------
// k1b: reduce partials over h into 16 region sums + global sum.
// grid = B*17 blocks, 128 threads. __ldcs: g_partial dead after this and must
// not evict the LRU-resident feature tail.
// ---------------------------------------------------------------------------
__global__ __launch_bounds__(128) void k1b_reduce() {
    const int b = blockIdx.x / 17;
    const int r = blockIdx.x % 17;
    const int t = threadIdx.x;

    float4 acc = make_float4(0.f, 0.f, 0.f, 0.f);
    if (r < 16) {
        const int i  = r >> 2;     // h-region index
        const int j  = r & 3;      // w-region index
        const int h0 = 24 * i;     // h-region covers [24i, 24i+32)
        #pragma unroll 8
        for (int hh = 0; hh < 32; ++hh) {
            float4 v = __ldcs(&g_partial[((size_t)(b * HH + h0 + hh) * 5 + j) * DD4 + t]);
            acc = f4add(acc, v);
        }
    } else {
        #pragma unroll 8
        for (int h = 0; h < HH; ++h) {
            float4 v = __ldcs(&g_partial[((size_t)(b * HH + h) * 5 + 4) * DD4 + t]);
            acc = f4add(acc, v);
        }
    }
    g_sums[(size_t)(b * 17 + r) * DD4 + t] = acc;
}

// ---------------------------------------------------------------------------
// k2: elementwise pass with 32-DEEP burst groups: 32 loads then 32 stores
// (half the read<->write direction switches vs the 16-deep R13 winner).
// grid = B*H = 1024 blocks, 256 threads: threadIdx = s*128 + t
//   t = d4 lane, s = w-half (s=0 -> high half [64,128), s=1 -> low [0,64)).
// Each thread: 64 w as 2 groups of 32, groups high-w first (tail harvest).
// Reads __ldcs, stores __stcs (measured best policies).
// ---------------------------------------------------------------------------
__global__ __launch_bounds__(256) void k2_apply(const float4* __restrict__ feat,
                                                float4* __restrict__ out) {
    const int bh = blockIdx.x;
    const int b  = bh >> 7;
    const int h  = bh & 127;
    const int t  = threadIdx.x & 127;   // d4 lane
    const int s  = threadIdx.x >> 7;    // w-half selector

    __shared__ float4 s_wc[WWD];        // {ww0..ww3} * coef, per w

    // per-h Gaussian weights (uniform across block)
    const float hc = h * (3.0f / 127.0f);
    float hwv[4];
    float HS = 0.f;
    #pragma unroll
    for (int i = 0; i < 4; ++i) {
        float d = hc - (float)i;
        hwv[i] = __expf(-0.125f * d * d);
        HS += hwv[i];
    }

    if (threadIdx.x < WWD) {
        const int w = threadIdx.x;
        const float wc = w * (3.0f / 127.0f);
        float e[4];
        float WS = 0.f;
        #pragma unroll
        for (int j = 0; j < 4; ++j) {
            float d = wc - (float)j;
            e[j] = __expf(-0.125f * d * d);
            WS += e[j];
        }
        const float c = 0.6f / (1024.0f * (HS * WS + 1e-8f));
        s_wc[w] = make_float4(e[0] * c, e[1] * c, e[2] * c, e[3] * c);
    }
    __syncthreads();

    // colagg[j] + global term for this d4 lane (g_sums tiny, L2-hot)
    const float4* srow = g_sums + (size_t)b * 17 * DD4 + t;
    float4 ca[4];
    #pragma unroll
    for (int j = 0; j < 4; ++j) ca[j] = make_float4(0.f, 0.f, 0.f, 0.f);
    #pragma unroll
    for (int i = 0; i < 4; ++i)
        #pragma unroll
        for (int j = 0; j < 4; ++j)
            ca[j] = f4fma(hwv[i], srow[(i * 4 + j) * DD4], ca[j]);

    float4 gs = srow[16 * DD4];
    const float gscale = 0.4f / 16384.0f;
    float4 base = make_float4(gs.x * gscale, gs.y * gscale, gs.z * gscale, gs.w * gscale);

    // Half assignment: s=0 takes high w-half (L2 tail) first.
    const int w0 = (1 - s) * 64;        // start of this thread's 64-w range
    const float4* frow = feat + (size_t)bh * WWD * DD4 + t;
    float4*       orow = out  + (size_t)bh * WWD * DD4 + t;

    // 2 groups of 32, processed high-w first within the half.
    #pragma unroll
    for (int g = 1; g >= 0; --g) {
        const int wb = w0 + g * 32;
        float4 v[32];
        #pragma unroll
        for (int k = 0; k < 32; ++k)
            v[k] = __ldcs(&frow[(size_t)(wb + k) * DD4]);

        #pragma unroll
        for (int k = 0; k < 32; ++k) {
            const float4 wc = s_wc[wb + k];
            float4 r;
            r.x = v[k].x + base.x + wc.x * ca[0].x + wc.y * ca[1].x + wc.z * ca[2].x + wc.w * ca[3].x;
            r.y = v[k].y + base.y + wc.x * ca[0].y + wc.y * ca[1].y + wc.z * ca[2].y + wc.w * ca[3].y;
            r.z = v[k].z + base.z + wc.x * ca[0].z + wc.y * ca[1].z + wc.z * ca[2].z + wc.w * ca[3].z;
            r.w = v[k].w + base.w + wc.x * ca[0].w + wc.y * ca[1].w + wc.z * ca[2].w + wc.w * ca[3].w;
            __stcs(&orow[(size_t)(wb + k) * DD4], r);
        }
    }
}

// ---------------------------------------------------------------------------
extern "C" void kernel_launch(void* const* d_in, const int* in_sizes, int n_in,
                              void* d_out, int out_size) {
    const float4* feat = (const float4*)d_in[0];
    float4*       out  = (float4*)d_out;

    k1_rowsums<<<BB * HH, 128>>>(feat);
    k1b_reduce<<<BB * 17, 128>>>();
    k2_apply<<<BB * HH, 256>>>(feat, out);
}

// round 15
// speedup vs baseline: 1.1232x; 1.1232x over previous
#include <cuda_runtime.h>

#define BB 8
#define HH 128
#define WWD 128
#define DD4 128          // D / 4 (float4 lanes)

// Scratch (allocation-free rule: __device__ globals)
__device__ float4 g_partial[BB * HH * 5 * DD4];  // [b][h][k][d4], k=0..3 w-region sums, k=4 full row
__device__ float4 g_sums[BB * 17 * DD4];         // [b][r][d4], r=0..15 region sums, r=16 global

__device__ __forceinline__ float4 f4add(float4 a, float4 b) {
    return make_float4(a.x + b.x, a.y + b.y, a.z + b.z, a.w + b.w);
}
__device__ __forceinline__ float4 f4fma(float s, float4 a, float4 b) {
    return make_float4(fmaf(s, a.x, b.x), fmaf(s, a.y, b.y),
                       fmaf(s, a.z, b.z), fmaf(s, a.w, b.w));
}

// ---------------------------------------------------------------------------
// k1: per (b,h) row — per-w-region partial sums + full row sum.
// grid = B*H = 1024 blocks, 128 threads. Proven fastest form.
// ---------------------------------------------------------------------------
__global__ __launch_bounds__(128) void k1_rowsums(const float4* __restrict__ feat) {
    const int bh = blockIdx.x;                 // b*128 + h
    const int t  = threadIdx.x;                // d4 lane
    const float4* row = feat + (size_t)bh * WWD * DD4 + t;

    float4 a0 = make_float4(0.f, 0.f, 0.f, 0.f);
    float4 a1 = a0, a2 = a0, a3 = a0, af = a0;

    #pragma unroll 8
    for (int w = 0; w < WWD; ++w) {
        float4 v = __ldg(&row[(size_t)w * DD4]);
        af = f4add(af, v);
        // region j covers w in [24j, 24j+32)
        if (w < 32)             a0 = f4add(a0, v);
        if (w >= 24 && w < 56)  a1 = f4add(a1, v);
        if (w >= 48 && w < 80)  a2 = f4add(a2, v);
        if (w >= 72 && w < 104) a3 = f4add(a3, v);
    }

    float4* p = g_partial + (size_t)bh * 5 * DD4 + t;
    p[0 * DD4] = a0;
    p[1 * DD4] = a1;
    p[2 * DD4] = a2;
    p[3 * DD4] = a3;
    p[4 * DD4] = af;
}

// ---------------------------------------------------------------------------
// k1b: reduce partials over h into 16 region sums + global sum.
// grid = B*17 blocks, 128 threads. __ldcs: g_partial dead after this and must
// not evict the LRU-resident feature tail.
// ---------------------------------------------------------------------------
__global__ __launch_bounds__(128) void k1b_reduce() {
    const int b = blockIdx.x / 17;
    const int r = blockIdx.x % 17;
    const int t = threadIdx.x;

    float4 acc = make_float4(0.f, 0.f, 0.f, 0.f);
    if (r < 16) {
        const int i  = r >> 2;     // h-region index
        const int j  = r & 3;      // w-region index
        const int h0 = 24 * i;     // h-region covers [24i, 24i+32)
        #pragma unroll 8
        for (int hh = 0; hh < 32; ++hh) {
            float4 v = __ldcs(&g_partial[((size_t)(b * HH + h0 + hh) * 5 + j) * DD4 + t]);
            acc = f4add(acc, v);
        }
    } else {
        #pragma unroll 8
        for (int h = 0; h < HH; ++h) {
            float4 v = __ldcs(&g_partial[((size_t)(b * HH + h) * 5 + 4) * DD4 + t]);
            acc = f4add(acc, v);
        }
    }
    g_sums[(size_t)(b * 17 + r) * DD4 + t] = acc;
}

// ---------------------------------------------------------------------------
// k2: elementwise pass, 16-DEEP burst groups (R13 sweet spot: 2 blocks/SM,
// 16 warps keep both DRAM directions fed).
// grid = B*H = 1024 blocks, 256 threads: threadIdx = s*128 + t
//   t = d4 lane, s = w-half (s=0 -> high half [64,128), s=1 -> low [0,64)).
// Each thread: 64 w as 4 groups of 16, groups high-w first (tail harvest).
// Reads __ldcs; stores __stwt (write-through: no L2 write-allocate, output
// never re-read, full 128B sectors per warp).
// ---------------------------------------------------------------------------
__global__ __launch_bounds__(256) void k2_apply(const float4* __restrict__ feat,
                                                float4* __restrict__ out) {
    const int bh = blockIdx.x;
    const int b  = bh >> 7;
    const int h  = bh & 127;
    const int t  = threadIdx.x & 127;   // d4 lane
    const int s  = threadIdx.x >> 7;    // w-half selector

    __shared__ float4 s_wc[WWD];        // {ww0..ww3} * coef, per w

    // per-h Gaussian weights (uniform across block)
    const float hc = h * (3.0f / 127.0f);
    float hwv[4];
    float HS = 0.f;
    #pragma unroll
    for (int i = 0; i < 4; ++i) {
        float d = hc - (float)i;
        hwv[i] = __expf(-0.125f * d * d);
        HS += hwv[i];
    }

    if (threadIdx.x < WWD) {
        const int w = threadIdx.x;
        const float wc = w * (3.0f / 127.0f);
        float e[4];
        float WS = 0.f;
        #pragma unroll
        for (int j = 0; j < 4; ++j) {
            float d = wc - (float)j;
            e[j] = __expf(-0.125f * d * d);
            WS += e[j];
        }
        const float c = 0.6f / (1024.0f * (HS * WS + 1e-8f));
        s_wc[w] = make_float4(e[0] * c, e[1] * c, e[2] * c, e[3] * c);
    }
    __syncthreads();

    // colagg[j] + global term for this d4 lane (g_sums tiny, L2-hot)
    const float4* srow = g_sums + (size_t)b * 17 * DD4 + t;
    float4 ca[4];
    #pragma unroll
    for (int j = 0; j < 4; ++j) ca[j] = make_float4(0.f, 0.f, 0.f, 0.f);
    #pragma unroll
    for (int i = 0; i < 4; ++i)
        #pragma unroll
        for (int j = 0; j < 4; ++j)
            ca[j] = f4fma(hwv[i], srow[(i * 4 + j) * DD4], ca[j]);

    float4 gs = srow[16 * DD4];
    const float gscale = 0.4f / 16384.0f;
    float4 base = make_float4(gs.x * gscale, gs.y * gscale, gs.z * gscale, gs.w * gscale);

    // Half assignment: s=0 takes high w-half (L2 tail) first.
    const int w0 = (1 - s) * 64;        // start of this thread's 64-w range
    const float4* frow = feat + (size_t)bh * WWD * DD4 + t;
    float4*       orow = out  + (size_t)bh * WWD * DD4 + t;

    // 4 groups of 16, processed high-w first within the half.
    #pragma unroll
    for (int g = 3; g >= 0; --g) {
        const int wb = w0 + g * 16;
        float4 v[16];
        #pragma unroll
        for (int k = 0; k < 16; ++k)
            v[k] = __ldcs(&frow[(size_t)(wb + k) * DD4]);

        #pragma unroll
        for (int k = 0; k < 16; ++k) {
            const float4 wc = s_wc[wb + k];
            float4 r;
            r.x = v[k].x + base.x + wc.x * ca[0].x + wc.y * ca[1].x + wc.z * ca[2].x + wc.w * ca[3].x;
            r.y = v[k].y + base.y + wc.x * ca[0].y + wc.y * ca[1].y + wc.z * ca[2].y + wc.w * ca[3].y;
            r.z = v[k].z + base.z + wc.x * ca[0].z + wc.y * ca[1].z + wc.z * ca[2].z + wc.w * ca[3].z;
            r.w = v[k].w + base.w + wc.x * ca[0].w + wc.y * ca[1].w + wc.z * ca[2].w + wc.w * ca[3].w;
            __stwt(&orow[(size_t)(wb + k) * DD4], r);
        }
    }
}

// ---------------------------------------------------------------------------
extern "C" void kernel_launch(void* const* d_in, const int* in_sizes, int n_in,
                              void* d_out, int out_size) {
    const float4* feat = (const float4*)d_in[0];
    float4*       out  = (float4*)d_out;

    k1_rowsums<<<BB * HH, 128>>>(feat);
    k1b_reduce<<<BB * 17, 128>>>();
    k2_apply<<<BB * HH, 256>>>(feat, out);
}

// round 16
// speedup vs baseline: 1.1728x; 1.0441x over previous
#include <cuda_runtime.h>

#define BB 8
#define HH 128
#define WWD 128
#define DD4 128          // D / 4 (float4 lanes)

// Scratch (allocation-free rule: __device__ globals)
__device__ float4 g_partial[BB * HH * 5 * DD4];  // [b][h][k][d4], k=0..3 w-region sums, k=4 full row
__device__ float4 g_sums[BB * 17 * DD4];         // [b][r][d4], r=0..15 region sums, r=16 global

__device__ __forceinline__ float4 f4add(float4 a, float4 b) {
    return make_float4(a.x + b.x, a.y + b.y, a.z + b.z, a.w + b.w);
}
__device__ __forceinline__ float4 f4fma(float s, float4 a, float4 b) {
    return make_float4(fmaf(s, a.x, b.x), fmaf(s, a.y, b.y),
                       fmaf(s, a.z, b.z), fmaf(s, a.w, b.w));
}

// ---------------------------------------------------------------------------
// k1: per (b,h) row — per-w-region partial sums + full row sum.
// grid = B*H = 1024 blocks, 128 threads, unroll 8 (R15-measured best:
// 43.7us @ 6.24 TB/s).
// ---------------------------------------------------------------------------
__global__ __launch_bounds__(128) void k1_rowsums(const float4* __restrict__ feat) {
    const int bh = blockIdx.x;                 // b*128 + h
    const int t  = threadIdx.x;                // d4 lane
    const float4* row = feat + (size_t)bh * WWD * DD4 + t;

    float4 a0 = make_float4(0.f, 0.f, 0.f, 0.f);
    float4 a1 = a0, a2 = a0, a3 = a0, af = a0;

    #pragma unroll 8
    for (int w = 0; w < WWD; ++w) {
        float4 v = __ldg(&row[(size_t)w * DD4]);
        af = f4add(af, v);
        // region j covers w in [24j, 24j+32)
        if (w < 32)             a0 = f4add(a0, v);
        if (w >= 24 && w < 56)  a1 = f4add(a1, v);
        if (w >= 48 && w < 80)  a2 = f4add(a2, v);
        if (w >= 72 && w < 104) a3 = f4add(a3, v);
    }

    float4* p = g_partial + (size_t)bh * 5 * DD4 + t;
    p[0 * DD4] = a0;
    p[1 * DD4] = a1;
    p[2 * DD4] = a2;
    p[3 * DD4] = a3;
    p[4 * DD4] = af;
}

// ---------------------------------------------------------------------------
// k1b: reduce partials over h into 16 region sums + global sum.
// grid = B*17 blocks, 128 threads. __ldcs: g_partial dead after this and must
// not evict the LRU-resident feature tail.
// ---------------------------------------------------------------------------
__global__ __launch_bounds__(128) void k1b_reduce() {
    const int b = blockIdx.x / 17;
    const int r = blockIdx.x % 17;
    const int t = threadIdx.x;

    float4 acc = make_float4(0.f, 0.f, 0.f, 0.f);
    if (r < 16) {
        const int i  = r >> 2;     // h-region index
        const int j  = r & 3;      // w-region index
        const int h0 = 24 * i;     // h-region covers [24i, 24i+32)
        #pragma unroll 8
        for (int hh = 0; hh < 32; ++hh) {
            float4 v = __ldcs(&g_partial[((size_t)(b * HH + h0 + hh) * 5 + j) * DD4 + t]);
            acc = f4add(acc, v);
        }
    } else {
        #pragma unroll 8
        for (int h = 0; h < HH; ++h) {
            float4 v = __ldcs(&g_partial[((size_t)(b * HH + h) * 5 + 4) * DD4 + t]);
            acc = f4add(acc, v);
        }
    }
    g_sums[(size_t)(b * 17 + r) * DD4 + t] = acc;
}

// ---------------------------------------------------------------------------
// k2: elementwise pass — EXACT R13 winner form (~93us measured).
// 16-deep burst groups: 16 __ldcs then 16 FMA+__stcs per group.
// grid = B*H = 1024 blocks, 256 threads: threadIdx = s*128 + t
//   t = d4 lane, s = w-half (s=0 -> high half [64,128), s=1 -> low [0,64)).
// 2 blocks/SM (~104 regs), 16 warps keep both DRAM directions fed.
// ---------------------------------------------------------------------------
__global__ __launch_bounds__(256) void k2_apply(const float4* __restrict__ feat,
                                                float4* __restrict__ out) {
    const int bh = blockIdx.x;
    const int b  = bh >> 7;
    const int h  = bh & 127;
    const int t  = threadIdx.x & 127;   // d4 lane
    const int s  = threadIdx.x >> 7;    // w-half selector

    __shared__ float4 s_wc[WWD];        // {ww0..ww3} * coef, per w

    // per-h Gaussian weights (uniform across block)
    const float hc = h * (3.0f / 127.0f);
    float hwv[4];
    float HS = 0.f;
    #pragma unroll
    for (int i = 0; i < 4; ++i) {
        float d = hc - (float)i;
        hwv[i] = __expf(-0.125f * d * d);
        HS += hwv[i];
    }

    if (threadIdx.x < WWD) {
        const int w = threadIdx.x;
        const float wc = w * (3.0f / 127.0f);
        float e[4];
        float WS = 0.f;
        #pragma unroll
        for (int j = 0; j < 4; ++j) {
            float d = wc - (float)j;
            e[j] = __expf(-0.125f * d * d);
            WS += e[j];
        }
        const float c = 0.6f / (1024.0f * (HS * WS + 1e-8f));
        s_wc[w] = make_float4(e[0] * c, e[1] * c, e[2] * c, e[3] * c);
    }
    __syncthreads();

    // colagg[j] + global term for this d4 lane (g_sums tiny, L2-hot)
    const float4* srow = g_sums + (size_t)b * 17 * DD4 + t;
    float4 ca[4];
    #pragma unroll
    for (int j = 0; j < 4; ++j) ca[j] = make_float4(0.f, 0.f, 0.f, 0.f);
    #pragma unroll
    for (int i = 0; i < 4; ++i)
        #pragma unroll
        for (int j = 0; j < 4; ++j)
            ca[j] = f4fma(hwv[i], srow[(i * 4 + j) * DD4], ca[j]);

    float4 gs = srow[16 * DD4];
    const float gscale = 0.4f / 16384.0f;
    float4 base = make_float4(gs.x * gscale, gs.y * gscale, gs.z * gscale, gs.w * gscale);

    // Half assignment: s=0 takes high w-half (L2 tail) first.
    const int w0 = (1 - s) * 64;        // start of this thread's 64-w range
    const float4* frow = feat + (size_t)bh * WWD * DD4 + t;
    float4*       orow = out  + (size_t)bh * WWD * DD4 + t;

    // 4 groups of 16, processed high-w first within the half.
    #pragma unroll
    for (int g = 3; g >= 0; --g) {
        const int wb = w0 + g * 16;
        float4 v[16];
        #pragma unroll
        for (int k = 0; k < 16; ++k)
            v[k] = __ldcs(&frow[(size_t)(wb + k) * DD4]);

        #pragma unroll
        for (int k = 0; k < 16; ++k) {
            const float4 wc = s_wc[wb + k];
            float4 r;
            r.x = v[k].x + base.x + wc.x * ca[0].x + wc.y * ca[1].x + wc.z * ca[2].x + wc.w * ca[3].x;
            r.y = v[k].y + base.y + wc.x * ca[0].y + wc.y * ca[1].y + wc.z * ca[2].y + wc.w * ca[3].y;
            r.z = v[k].z + base.z + wc.x * ca[0].z + wc.y * ca[1].z + wc.z * ca[2].z + wc.w * ca[3].z;
            r.w = v[k].w + base.w + wc.x * ca[0].w + wc.y * ca[1].w + wc.z * ca[2].w + wc.w * ca[3].w;
            __stcs(&orow[(size_t)(wb + k) * DD4], r);
        }
    }
}

// ---------------------------------------------------------------------------
extern "C" void kernel_launch(void* const* d_in, const int* in_sizes, int n_in,
                              void* d_out, int out_size) {
    const float4* feat = (const float4*)d_in[0];
    float4*       out  = (float4*)d_out;

    k1_rowsums<<<BB * HH, 128>>>(feat);
    k1b_reduce<<<BB * 17, 128>>>();
    k2_apply<<<BB * HH, 256>>>(feat, out);
}